// round 5
// baseline (speedup 1.0000x reference)
#include <cuda_runtime.h>
#include <cuda_bf16.h>

#define NN 16384      // nodes/edges (and bond_n rows A = 16384)
#define DD 128        // emb dim
// Only layer i = 2 matters: the reference loop does not feed h back.

#define NBLK 296      // 2 blocks per SM on 148 SMs -> ALL co-resident (grid bar safe)

// Scratch (device globals — zero-initialized at module load)
__device__ float g_part[NBLK][NN];           // per-block column partial sums (19.4 MB)
__device__ float g_colw[NN];
__device__ float g_mpartT[DD][128];          // m partials, contiguous per d
__device__ unsigned g_c[3];                  // grid-barrier counters (monotonic per run)
__device__ unsigned g_done;                  // exit counter (resets g_c for replay)

// Grid barrier: every block arrives; only blocks with `wait` spin until all did.
__device__ __forceinline__ void grid_bar(unsigned* c, bool wait) {
    __syncthreads();
    if (threadIdx.x == 0) {
        __threadfence();
        atomicAdd(c, 1u);
        if (wait) {
            while (atomicAdd(c, 0u) < NBLK) __nanosleep(64);
            __threadfence();
        }
    }
    __syncthreads();
}

// ---------------------------------------------------------------------------
// Single persistent kernel. Phases:
//  P1: blocks [0,128) GEMM h_n -> SMEM (never DRAM); then all 296 blocks
//      stream static shares of bond_n rows -> g_part (deterministic).
//  P2: blocks [0,256) reduce g_part -> g_colw (64 cols each, high-MLP).
//  P3: GEMM blocks: m partial from SMEM h_n -> g_mpartT.
//  P4: GEMM blocks: reduce m (L2-hot) + mm GEMV + out = relu(h_n + mm).
// ---------------------------------------------------------------------------
__global__ void __launch_bounds__(256, 2) k_all(
    const float* __restrict__ bn,
    const int* __restrict__ x, const int* __restrict__ ea,
    const float* __restrict__ aemb, const float* __restrict__ bemb,
    const float* __restrict__ Wi_w2, const float* __restrict__ Wi_b2,
    const float* __restrict__ Wm_w2, const float* __restrict__ Wm_b2,
    float* __restrict__ out)
{
    extern __shared__ float sm[];               // 65,792 B dynamic
    __shared__ float red[256];
    __shared__ float mm_s[128];
    __shared__ float colw_s[128];
    __shared__ float bias_s[128];
    __shared__ int xi0[128], xi1[128], ei0[128], ei1[128];
    __shared__ float4 sred[16][16];

    const int tid = threadIdx.x;
    const int bid = blockIdx.x;
    const bool isGemm = (bid < 128);

    // ---- static row shares for the bond_n stream (sum = 16384) ----
    int start, cnt;
    if (bid < 128)          { start = bid * 51;                 cnt = 51; }
    else if (bid < 240)     { start = 6528  + (bid - 128) * 59; cnt = 59; }
    else                    { start = 13136 + (bid - 240) * 58; cnt = 58; }

    // =============== P1a: GEMM (blocks 0..127), result -> SMEM ===============
    if (isGemm) {
        float* w_s   = sm;                 // [64][129] = 33,024 B (per-k chunk)
        float* cat_s = sm + 64 * 129;      // [128][64] = 32,768 B
        const int rowBase = bid * 128;

        if (tid < 128) {
            bias_s[tid] = Wi_b2[tid];
            int r = rowBase + tid;
            xi0[tid] = x[2 * r];  xi1[tid] = x[2 * r + 1];
            ei0[tid] = ea[2 * r]; ei1[tid] = ea[2 * r + 1];
        }
        __syncthreads();

        const int tx = tid & 15, ty = tid >> 4;
        float acc[8][8];
#pragma unroll
        for (int i = 0; i < 8; i++)
#pragma unroll
            for (int j = 0; j < 8; j++) acc[i][j] = 0.f;

        for (int kc = 0; kc < 256; kc += 64) {
            for (int idx = tid; idx < 8192; idx += 256) {
                int d = idx >> 6, kk = idx & 63;
                w_s[kk * 129 + d] = Wi_w2[d * 256 + kc + kk];
            }
            const bool atom = (kc < 128);
            const float* emb = atom ? aemb : bemb;
            for (int idx = tid; idx < 2048; idx += 256) {
                int row  = idx >> 4;
                int kloc = (idx & 15) * 4;
                int i0 = atom ? xi0[row] : ei0[row];
                int i1 = atom ? xi1[row] : ei1[row];
                int ko = atom ? (kc + kloc) : (kc - 128 + kloc);
                float4 v0 = *(const float4*)(emb + i0 * 128 + ko);
                float4 v1 = *(const float4*)(emb + i1 * 128 + ko);
                float4 s;
                s.x = v0.x + v1.x; s.y = v0.y + v1.y;
                s.z = v0.z + v1.z; s.w = v0.w + v1.w;
                *(float4*)(cat_s + row * 64 + kloc) = s;
            }
            __syncthreads();

#pragma unroll 8
            for (int kk = 0; kk < 64; kk++) {
                const float* wr = w_s + kk * 129;
                float b[8], a[8];
#pragma unroll
                for (int j = 0; j < 8; j++) b[j] = wr[tx + 16 * j];
#pragma unroll
                for (int i = 0; i < 8; i++) a[i] = cat_s[(ty + 16 * i) * 64 + kk];
#pragma unroll
                for (int i = 0; i < 8; i++)
#pragma unroll
                    for (int j = 0; j < 8; j++)
                        acc[i][j] = fmaf(a[i], b[j], acc[i][j]);
            }
            __syncthreads();
        }

        // bias + relu -> hn in SMEM (reuses w_s/cat_s space; k-loop is done)
        float* hn = sm;                    // [128][128] = 65,536 B
#pragma unroll
        for (int i = 0; i < 8; i++) {
            int r = ty + 16 * i;
#pragma unroll
            for (int j = 0; j < 8; j++) {
                int d = tx + 16 * j;
                float v = acc[i][j] + bias_s[d];
                hn[r * 128 + d] = v > 0.f ? v : 0.f;
            }
        }
        __syncthreads();
    }

    // =============== P1b: bond_n streaming (ALL blocks) ===============
    {
        float4 acc[16];
#pragma unroll
        for (int i = 0; i < 16; i++) acc[i] = make_float4(0.f, 0.f, 0.f, 0.f);

        for (int r = 0; r < cnt; r++) {
            const float4* rp = (const float4*)(bn + (size_t)(start + r) * NN) + tid;
#pragma unroll
            for (int i = 0; i < 16; i++) {
                float4 v = __ldcs(rp + i * 256);
                acc[i].x += v.x; acc[i].y += v.y; acc[i].z += v.z; acc[i].w += v.w;
            }
        }
        float4* dst = (float4*)g_part[bid] + tid;
#pragma unroll
        for (int i = 0; i < 16; i++) dst[i * 256] = acc[i];
    }

    grid_bar(&g_c[0], /*wait=*/bid < 256);

    // =============== P2: colw reduce (blocks 0..255, 64 cols each) ===============
    if (bid < 256) {
        const int seg = tid >> 4;          // 0..15 (u segment over 296 partials)
        const int c4  = tid & 15;          // 0..15 (float4 column group)
        const int u0  = (seg < 8) ? 19 * seg : 152 + 18 * (seg - 8);
        const int un  = (seg < 8) ? 19 : 18;
        float4 s = make_float4(0.f, 0.f, 0.f, 0.f);
#pragma unroll 19
        for (int i = 0; i < un; i++) {
            float4 v = __ldcs((const float4*)(&g_part[u0 + i][bid * 64]) + c4);
            s.x += v.x; s.y += v.y; s.z += v.z; s.w += v.w;
        }
        sred[seg][c4] = s;
        __syncthreads();
        if (tid < 16) {
            float4 t = make_float4(0.f, 0.f, 0.f, 0.f);
#pragma unroll
            for (int g = 0; g < 16; g++) {
                float4 v = sred[g][tid];
                t.x += v.x; t.y += v.y; t.z += v.z; t.w += v.w;
            }
            *(float4*)(g_colw + bid * 64 + tid * 4) = t;
        }
    }

    grid_bar(&g_c[1], /*wait=*/isGemm);
    if (!isGemm) {
        // non-GEMM blocks: arrive at remaining barrier, bump done, exit
        grid_bar(&g_c[2], false);
        __syncthreads();
        if (tid == 0) {
            unsigned r = atomicAdd(&g_done, 1u);
            if (r == NBLK - 1u) {
                g_c[0] = 0u; g_c[1] = 0u; g_c[2] = 0u;
                __threadfence();
                g_done = 0u;
            }
        }
        return;
    }

    // =============== P3: m partial from SMEM h_n (GEMM blocks) ===============
    const float* hn = sm;
    const int rowBase = bid * 128;
    if (tid < 128) colw_s[tid] = g_colw[rowBase + tid];
    __syncthreads();
    {
        const int d = tid & 127, half = tid >> 7;
        float p = 0.f;
#pragma unroll 8
        for (int r = 0; r < 64; r++) {
            int row = half * 64 + r;
            p = fmaf(colw_s[row], hn[row * 128 + d], p);
        }
        red[tid] = p;
    }
    __syncthreads();
    if (tid < 128) g_mpartT[tid][bid] = red[tid] + red[tid + 128];

    grid_bar(&g_c[2], /*wait=*/true);

    // =============== P4: m reduce + mm GEMV (redundant per block, L2-hot) =====
    if (tid < 128) {
        const float4* mp = (const float4*)g_mpartT[tid];
        float s = 0.f;
#pragma unroll 32
        for (int w = 0; w < 32; w++) {
            float4 v = __ldcg(mp + w);
            s += v.x + v.y + v.z + v.w;
        }
        red[tid] = s;        // red = m
    }
    __syncthreads();
    if (tid < 128) {
        float s = Wm_b2[tid];
        const float* row = Wm_w2 + tid * 128;
#pragma unroll 8
        for (int k = 0; k < 128; k++) s = fmaf(red[k], __ldg(row + k), s);
        mm_s[tid] = s;
    }
    __syncthreads();

    // out = relu(h_n + mm), straight from SMEM, coalesced float4
    {
        float4* ob = (float4*)(out + (size_t)rowBase * 128);
        for (int i = tid; i < 4096; i += 256) {
            int row = i >> 5, dg = (i & 31) * 4;
            float4 v = *(const float4*)(hn + row * 128 + dg);
            v.x = fmaxf(v.x + mm_s[dg + 0], 0.f);
            v.y = fmaxf(v.y + mm_s[dg + 1], 0.f);
            v.z = fmaxf(v.z + mm_s[dg + 2], 0.f);
            v.w = fmaxf(v.w + mm_s[dg + 3], 0.f);
            ob[i] = v;
        }
    }

    __syncthreads();
    if (tid == 0) {
        unsigned r = atomicAdd(&g_done, 1u);
        if (r == NBLK - 1u) {
            g_c[0] = 0u; g_c[1] = 0u; g_c[2] = 0u;
            __threadfence();
            g_done = 0u;
        }
    }
}

// ---------------------------------------------------------------------------
extern "C" void kernel_launch(void* const* d_in, const int* in_sizes, int n_in,
                              void* d_out, int out_size) {
    const int*   x    = (const int*)d_in[0];
    const int*   ea   = (const int*)d_in[1];
    const float* bn   = (const float*)d_in[2];
    const float* aemb = (const float*)d_in[3];
    const float* bemb = (const float*)d_in[4];
    const float* Wi_w = (const float*)d_in[5];
    const float* Wi_b = (const float*)d_in[6];
    const float* Wm_w = (const float*)d_in[7];
    const float* Wm_b = (const float*)d_in[8];

    // Only the last layer (i = 2) affects the output.
    const float* Wi_w2 = Wi_w + 2 * 128 * 256;
    const float* Wi_b2 = Wi_b + 2 * 128;
    const float* Wm_w2 = Wm_w + 2 * 128 * 128;
    const float* Wm_b2 = Wm_b + 2 * 128;

    const int smem = (64 * 129 + 128 * 64) * (int)sizeof(float);  // 65,792 B
    static bool attr_set = false;
    if (!attr_set) {
        cudaFuncSetAttribute(k_all, cudaFuncAttributeMaxDynamicSharedMemorySize, smem);
        attr_set = true;
    }

    k_all<<<NBLK, 256, smem>>>(bn, x, ea, aemb, bemb,
                               Wi_w2, Wi_b2, Wm_w2, Wm_b2, (float*)d_out);
}